// round 14
// baseline (speedup 1.0000x reference)
#include <cuda_runtime.h>
#include <cstdint>
#include <stdint.h>
#include <math.h>

#define NN 1024
#define HH 256
#define D0 71
#define BB 16
#define PP 523776   // NN*(NN-1)/2
#define NTILE 136
#define CSZ 8       // cluster size (CTAs per batch)
#define LCTAS (BB * CSZ)        // 128 logits CTAs
#define PFCTAS 1024             // prefetch CTAs (128 clusters of 8)
// total u lines = BB*PP*8/128 = 523776 (fits: 1024*256*2 = 524288 slots)

__device__ float g_c[BB];

struct Ptrs { const float* p[30]; };

__device__ __forceinline__ float geluf(float x) {
    return 0.5f * x * (1.0f + erff(x * 0.70710678118654752440f));
}

__device__ __forceinline__ unsigned s2u(const void* p) {
    unsigned a;
    asm("{ .reg .u64 t; cvta.to.shared.u64 t, %1; cvt.u32.u64 %0, t; }"
        : "=r"(a) : "l"(p));
    return a;
}

__device__ __forceinline__ unsigned ctarank() {
    unsigned r; asm("mov.u32 %0, %%cluster_ctarank;" : "=r"(r)); return r;
}

#define CLUSTER_SYNC() do { \
    asm volatile("barrier.cluster.arrive.aligned;" ::: "memory"); \
    asm volatile("barrier.cluster.wait.aligned;"   ::: "memory"); \
} while (0)

__device__ __forceinline__ void l2pf(const void* p) {
    asm volatile("prefetch.global.L2 [%0];" :: "l"(p));
}
// partition prefetch of nlines 128B lines across the 128 logits blocks
__device__ __forceinline__ void pfr(const float* w, int nlines) {
    const int l = blockIdx.x + (threadIdx.x << 7);
    if (l < nlines) l2pf((const char*)w + (size_t)l * 128);
}

// broadcast this CTA's 32-row slice of arr[256] to the other 7 cluster CTAs
__device__ __forceinline__ void bcast32(float* arr, int rank) {
    const int tid = threadIdx.x;
    if (tid < 32) {
        const int idx = (rank << 5) + tid;
        const float v = arr[idx];
        const unsigned la = s2u(&arr[idx]);
        #pragma unroll
        for (int p = 0; p < CSZ; p++) {
            if (p != rank) {
                unsigned ra;
                asm volatile("mapa.shared::cluster.u32 %0, %1, %2;"
                             : "=r"(ra) : "r"(la), "r"(p));
                asm volatile("st.shared::cluster.f32 [%0], %1;"
                             :: "r"(ra), "f"(v) : "memory");
            }
        }
    }
}

// block reduce over 256 threads (8 warps)
__device__ __forceinline__ float bred8(float v, float* red) {
    #pragma unroll
    for (int o = 16; o > 0; o >>= 1) v += __shfl_down_sync(0xffffffffu, v, o);
    const int lane = threadIdx.x & 31, wp = threadIdx.x >> 5;
    if (lane == 0) red[wp] = v;
    __syncthreads();
    if (wp == 0) {
        float s = (lane < 8) ? red[lane] : 0.0f;
        #pragma unroll
        for (int o = 4; o > 0; o >>= 1) s += __shfl_down_sync(0xffffffffu, s, o);
        if (lane == 0) red[0] = s;
    }
    __syncthreads();
    const float s = red[0];
    __syncthreads();
    return s;
}

__device__ __forceinline__ void ln256(const float* __restrict__ hv,
                                      const float* __restrict__ g,
                                      const float* __restrict__ bt,
                                      float* sa, float* red) {
    const int tid = threadIdx.x;
    const float v = hv[tid];
    const float m = bred8(v, red) * (1.0f / (float)HH);
    const float d = v - m;
    const float var = bred8(d * d, red) * (1.0f / (float)HH);
    const float rs = 1.0f / sqrtf(var + 1e-5f);
    sa[tid] = d * rs * g[tid] + bt[tid];
    __syncthreads();
}

// 71-dim LN stats via warp 0
__device__ __forceinline__ void ln71_stats(const float* __restrict__ zv, float* mv) {
    const int lane = threadIdx.x & 31, wp = threadIdx.x >> 5;
    if (wp == 0) {
        const float v0 = zv[lane], v1 = zv[lane + 32];
        const float v2 = (lane < D0 - 64) ? zv[lane + 64] : 0.f;
        float s = v0 + v1 + v2;
        #pragma unroll
        for (int o = 16; o; o >>= 1) s += __shfl_xor_sync(0xffffffffu, s, o);
        const float m = s / (float)D0;
        float q = (v0 - m) * (v0 - m) + (v1 - m) * (v1 - m);
        if (lane < D0 - 64) q += (v2 - m) * (v2 - m);
        #pragma unroll
        for (int o = 16; o; o >>= 1) q += __shfl_xor_sync(0xffffffffu, q, o);
        if (lane == 0) { mv[0] = m; mv[1] = 1.0f / sqrtf(q / (float)D0 + 1e-5f); }
    }
    __syncthreads();
}

// 32 rows of a 256x256 GEMV (this CTA's slice), 4 rows/warp.
// mode 0=plain, 1=gelu, 2=accumulate. Writes into outv[rank*32 .. +31].
__device__ __forceinline__ void gemv_slice(const float* __restrict__ w,
                                           const float* __restrict__ bias,
                                           const float* __restrict__ in,
                                           float* __restrict__ outv,
                                           int rank, int mode) {
    const int lane = threadIdx.x & 31, wp = threadIdx.x >> 5;
    const float4 a0 = ((const float4*)in)[lane];
    const float4 a1 = ((const float4*)in)[lane + 32];
    const int rb = (rank << 5) + (wp << 2);
    float4 x0[4], x1[4];
    #pragma unroll
    for (int r = 0; r < 4; r++) {
        const float4* w4 = (const float4*)w + (size_t)(rb + r) * 64;
        x0[r] = __ldg(&w4[lane]);
        x1[r] = __ldg(&w4[lane + 32]);
    }
    #pragma unroll
    for (int r = 0; r < 4; r++) {
        float s = x0[r].x * a0.x + x0[r].y * a0.y + x0[r].z * a0.z + x0[r].w * a0.w
                + x1[r].x * a1.x + x1[r].y * a1.y + x1[r].z * a1.z + x1[r].w * a1.w;
        #pragma unroll
        for (int o = 16; o; o >>= 1) s += __shfl_xor_sync(0xffffffffu, s, o);
        if (lane == 0) {
            const int row = rb + r;
            const float v = s + __ldg(&bias[row]);
            if (mode == 0) outv[row] = v;
            else if (mode == 1) outv[row] = geluf(v);
            else outv[row] += v;
        }
    }
    __syncthreads();
}

// Blocks 0..127: 16 clusters x 8 CTAs of logits work.
// Blocks 128..1151: prefetch the entire u array into L2, then exit.
__global__ void __launch_bounds__(256) __cluster_dims__(CSZ, 1, 1)
logits_cluster(Ptrs P, const char* __restrict__ uraw) {
    if (blockIdx.x >= LCTAS) {
        // u prefetch: 2 lines per thread, 523776 lines total
        const int base = (blockIdx.x - LCTAS) * 512 + threadIdx.x * 2;
        if (base < PP)     l2pf(uraw + (size_t)base * 128);
        if (base + 1 < PP) l2pf(uraw + (size_t)(base + 1) * 128);
        return;
    }

    const float* x     = P.p[0];  const float* stats = P.p[1];
    const float* ln0_g = P.p[3];  const float* ln0_b = P.p[4];
    const float* r1lg  = P.p[5];  const float* r1lb  = P.p[6];
    const float* r1w1  = P.p[7];  const float* r1b1  = P.p[8];
    const float* r1w2  = P.p[9];  const float* r1b2  = P.p[10];
    const float* r1wp  = P.p[11]; const float* r1bp  = P.p[12];
    const float* r2lg  = P.p[13]; const float* r2lb  = P.p[14];
    const float* r2w1  = P.p[15]; const float* r2b1  = P.p[16];
    const float* r2w2  = P.p[17]; const float* r2b2  = P.p[18];
    const float* alg   = P.p[19]; const float* alb   = P.p[20];
    const float* awin  = P.p[21]; const float* abin  = P.p[22];
    const float* awout = P.p[23]; const float* about_= P.p[24];
    const float* ow    = P.p[25]; const float* ob    = P.p[26];
    const float* fw    = P.p[27]; const float* fb    = P.p[28];

    const int b = blockIdx.x >> 3;
    const int rank = (int)ctarank();
    const int tid = threadIdx.x, lane = tid & 31, wp = tid >> 5;

    __shared__ __align__(16) float z[128], za[128];
    __shared__ __align__(16) float sa[HH], sb[HH], sh[HH], st[HH];
    __shared__ float red[8], mv[2];

    pfr(r1w1, 568);  pfr(r1wp, 568);
    pfr(r1w2, 2048); pfr(r2w1, 2048); pfr(r2w2, 2048);
    pfr(awin + 2 * HH * HH, 2048); pfr(awout, 2048); pfr(ow, 2048);

    // prologue (redundant per CTA): z, ln0, rb1-LN
    if (tid < 128) { z[tid] = 0.f; za[tid] = 0.f; }
    __syncthreads();
    if (tid < 64)      z[tid] = x[b * 64 + tid];
    else if (tid < D0) z[tid] = stats[b * 7 + tid - 64];
    __syncthreads();
    ln71_stats(z, mv);
    if (tid < D0) z[tid] = (z[tid] - mv[0]) * mv[1] * ln0_g[tid] + ln0_b[tid];
    __syncthreads();
    ln71_stats(z, mv);
    if (tid < D0) za[tid] = (z[tid] - mv[0]) * mv[1] * r1lg[tid] + r1lb[tid];
    __syncthreads();

    // Stage A: st = gelu(r1w1 @ za + b1)  [256x71], 32 rows/CTA (4/warp)
    {
        const float a0 = za[lane], a1 = za[lane + 32];
        const float a2 = (lane < D0 - 64) ? za[lane + 64] : 0.f;
        #pragma unroll
        for (int r = 0; r < 4; r++) {
            const int row = (rank << 5) + (wp << 2) + r;
            const float* wr = r1w1 + row * D0;
            float s = __ldg(&wr[lane]) * a0 + __ldg(&wr[lane + 32]) * a1;
            if (lane < D0 - 64) s += __ldg(&wr[lane + 64]) * a2;
            #pragma unroll
            for (int o = 16; o; o >>= 1) s += __shfl_xor_sync(0xffffffffu, s, o);
            if (lane == 0) st[row] = geluf(s + __ldg(&r1b1[row]));
        }
    }
    __syncthreads();
    bcast32(st, rank);
    CLUSTER_SYNC();

    // Stage B: sh = r1w2 @ st + r1wp @ z + b2 + bp
    {
        const float4 a0 = ((const float4*)st)[lane];
        const float4 a1 = ((const float4*)st)[lane + 32];
        const float z0 = z[lane], z1 = z[lane + 32];
        const float z2 = (lane < D0 - 64) ? z[lane + 64] : 0.f;
        #pragma unroll
        for (int r = 0; r < 4; r++) {
            const int row = (rank << 5) + (wp << 2) + r;
            const float* wr = r1wp + row * D0;
            float sp = __ldg(&wr[lane]) * z0 + __ldg(&wr[lane + 32]) * z1;
            if (lane < D0 - 64) sp += __ldg(&wr[lane + 64]) * z2;
            const float4* w4 = (const float4*)r1w2 + (size_t)row * 64;
            const float4 x0 = __ldg(&w4[lane]);
            const float4 x1 = __ldg(&w4[lane + 32]);
            float s = x0.x * a0.x + x0.y * a0.y + x0.z * a0.z + x0.w * a0.w
                    + x1.x * a1.x + x1.y * a1.y + x1.z * a1.z + x1.w * a1.w + sp;
            #pragma unroll
            for (int o = 16; o; o >>= 1) s += __shfl_xor_sync(0xffffffffu, s, o);
            if (lane == 0) sh[row] = s + __ldg(&r1b2[row]) + __ldg(&r1bp[row]);
        }
    }
    __syncthreads();
    bcast32(sh, rank);
    CLUSTER_SYNC();

    // rb2
    ln256(sh, r2lg, r2lb, sa, red);
    gemv_slice(r2w1, r2b1, sa, st, rank, 1);
    bcast32(st, rank);
    CLUSTER_SYNC();
    gemv_slice(r2w2, r2b2, st, sh, rank, 2);
    bcast32(sh, rank);
    CLUSTER_SYNC();

    // attention (tokens identical -> o == v)
    ln256(sh, alg, alb, sa, red);
    gemv_slice(awin + 2 * HH * HH, abin + 2 * HH, sa, st, rank, 0);
    bcast32(st, rank);
    CLUSTER_SYNC();
    gemv_slice(awout, about_, st, sb, rank, 0);
    bcast32(sb, rank);
    CLUSTER_SYNC();
    gemv_slice(ow, ob, sb, st, rank, 0);
    bcast32(st, rank);
    CLUSTER_SYNC();

    // final logits on rank 0 (st fully assembled)
    if (rank == 0) {
        const float hv = st[tid];
        const float f0 = __ldg(&fw[tid]) + __ldg(&fw[HH + tid]);
        const float f1 = __ldg(&fw[2 * HH + tid]) + __ldg(&fw[3 * HH + tid]);
        const float l0 = bred8(f0 * hv, red) + fb[0];
        const float l1 = bred8(f1 * hv, red) + fb[1];
        if (tid == 0) g_c[b] = expf(l1 - l0);
    }
}

// ---------- fill (R6-exact, byte-identical) ----------
__device__ __forceinline__ float edge_val(float ux, float uy, float cb) {
    const float w0 = 1e-10f - __logf(ux + 1e-10f);
    const float w1 = 1e-10f - __logf(uy + 1e-10f);
    const float cw0 = cb * w0;
    const float d = w1 - cw0;
    const float margin = 3e-6f * (fabsf(w1) + fabsf(cw0)) + 2e-7f;
    if (fabsf(d) > margin) return d >= 0.f ? 1.0f : 0.0f;
    const float e0 = 1e-10f - logf(ux + 1e-10f);
    const float e1 = 1e-10f - logf(uy + 1e-10f);
    return (e1 >= cb * e0) ? 1.0f : 0.0f;
}

__global__ void __launch_bounds__(256) fill_adj_kernel(const float2* __restrict__ u2,
                                                       float* __restrict__ out) {
    const int b = blockIdx.y;
    const int tl = blockIdx.x;
    int r = (int)((33.0f - sqrtf(1089.0f - 8.0f * (float)tl)) * 0.5f);
    while (r > 0 && r * (33 - r) / 2 > tl) r--;
    while ((r + 1) * (33 - (r + 1)) / 2 <= tl) r++;
    const int c = r + (tl - r * (33 - r) / 2);
    const int i0 = r << 6, j0 = c << 6;

    const float cb = g_c[b];
    const float2* __restrict__ ub = u2 + (size_t)b * PP;
    float* __restrict__ obp = out + (size_t)b * NN * NN;
    __shared__ float tile[64][65];   // stored TRANSPOSED: tile[jloc][iloc]

    const int tx = threadIdx.x;      // 0..15
    const int ty = threadIdx.y;      // 0..15

    if (i0 != j0) {
        #pragma unroll
        for (int rr = 0; rr < 4; rr++) {
            const int ti = ty + (rr << 4);
            const int i = i0 + ti;
            const int rowbase = (i * (2047 - i)) / 2 - i - 1 + j0;
            const int p0 = rowbase + 4 * tx;
            float4 ev;
            if (!(rowbase & 1)) {
                const float4* u4 = (const float4*)ub;
                const float4 A = __ldg(&u4[p0 >> 1]);
                const float4 Bq = __ldg(&u4[(p0 >> 1) + 1]);
                ev.x = edge_val(A.x,  A.y,  cb);
                ev.y = edge_val(A.z,  A.w,  cb);
                ev.z = edge_val(Bq.x, Bq.y, cb);
                ev.w = edge_val(Bq.z, Bq.w, cb);
            } else {
                const float2 a = __ldg(&ub[p0]);
                const float2 bq = __ldg(&ub[p0 + 1]);
                const float2 cq = __ldg(&ub[p0 + 2]);
                const float2 dq = __ldg(&ub[p0 + 3]);
                ev.x = edge_val(a.x,  a.y,  cb);
                ev.y = edge_val(bq.x, bq.y, cb);
                ev.z = edge_val(cq.x, cq.y, cb);
                ev.w = edge_val(dq.x, dq.y, cb);
            }
            *(float4*)&obp[(size_t)i * NN + j0 + 4 * tx] = ev;
            tile[4 * tx + 0][ti] = ev.x;
            tile[4 * tx + 1][ti] = ev.y;
            tile[4 * tx + 2][ti] = ev.z;
            tile[4 * tx + 3][ti] = ev.w;
        }
        __syncthreads();
        #pragma unroll
        for (int rr = 0; rr < 4; rr++) {
            const int tj = ty + (rr << 4);
            float4 f;
            f.x = tile[tj][4 * tx + 0];
            f.y = tile[tj][4 * tx + 1];
            f.z = tile[tj][4 * tx + 2];
            f.w = tile[tj][4 * tx + 3];
            *(float4*)&obp[(size_t)(j0 + tj) * NN + i0 + 4 * tx] = f;
        }
    } else {
        #pragma unroll
        for (int rr = 0; rr < 4; rr++) {
            const int ti = ty + (rr << 4);
            const int i = i0 + ti;
            const int rowbase = (i * (2047 - i)) / 2 - i - 1 + j0;
            #pragma unroll
            for (int k = 0; k < 4; k++) {
                const int col = 4 * tx + k;
                float e = 0.f;
                if (col > ti) {
                    const float2 uu = __ldg(&ub[rowbase + col]);
                    e = edge_val(uu.x, uu.y, cb);
                }
                tile[col][ti] = e;
                if (col >= ti) obp[(size_t)i * NN + j0 + col] = e;
            }
        }
        __syncthreads();
        #pragma unroll
        for (int rr = 0; rr < 4; rr++) {
            const int tj = ty + (rr << 4);
            #pragma unroll
            for (int k = 0; k < 4; k++) {
                const int col = 4 * tx + k;
                if (col < tj) obp[(size_t)(j0 + tj) * NN + i0 + col] = tile[tj][col];
            }
        }
    }
}

extern "C" void kernel_launch(void* const* d_in, const int* in_sizes, int n_in,
                              void* d_out, int out_size) {
    Ptrs P;
    for (int i = 0; i < 30; i++) P.p[i] = (const float*)d_in[i];

    logits_cluster<<<LCTAS + PFCTAS, 256>>>(P, (const char*)d_in[2]);

    dim3 grid(NTILE, BB), blk(16, 16);
    fill_adj_kernel<<<grid, blk>>>((const float2*)d_in[2], (float*)d_out);
}

// round 15
// speedup vs baseline: 1.0372x; 1.0372x over previous
#include <cuda_runtime.h>
#include <cstdint>
#include <stdint.h>
#include <math.h>

#define NN 1024
#define HH 256
#define D0 71
#define BB 16
#define PP 523776   // NN*(NN-1)/2
#define NTILE 136
#define CSZ 8       // cluster size (CTAs per batch)

__device__ float g_c[BB];

struct Ptrs { const float* p[30]; };

__device__ __forceinline__ float geluf(float x) {
    return 0.5f * x * (1.0f + erff(x * 0.70710678118654752440f));
}

__device__ __forceinline__ unsigned s2u(const void* p) {
    unsigned a;
    asm("{ .reg .u64 t; cvta.to.shared.u64 t, %1; cvt.u32.u64 %0, t; }"
        : "=r"(a) : "l"(p));
    return a;
}

__device__ __forceinline__ unsigned ctarank() {
    unsigned r; asm("mov.u32 %0, %%cluster_ctarank;" : "=r"(r)); return r;
}

#define CLUSTER_SYNC() do { \
    asm volatile("barrier.cluster.arrive.aligned;" ::: "memory"); \
    asm volatile("barrier.cluster.wait.aligned;"   ::: "memory"); \
} while (0)

__device__ __forceinline__ void l2pf(const void* p) {
    asm volatile("prefetch.global.L2 [%0];" :: "l"(p));
}
// partition prefetch of nlines 128B lines across the 128 logits blocks
__device__ __forceinline__ void pfr(const float* w, int nlines) {
    const int l = blockIdx.x + (threadIdx.x << 7);
    if (l < nlines) l2pf((const char*)w + (size_t)l * 128);
}

// broadcast this CTA's 32-row slice of arr[256] to the other 7 cluster CTAs
__device__ __forceinline__ void bcast32(float* arr, int rank) {
    const int tid = threadIdx.x;
    if (tid < 32) {
        const int idx = (rank << 5) + tid;
        const float v = arr[idx];
        const unsigned la = s2u(&arr[idx]);
        #pragma unroll
        for (int p = 0; p < CSZ; p++) {
            if (p != rank) {
                unsigned ra;
                asm volatile("mapa.shared::cluster.u32 %0, %1, %2;"
                             : "=r"(ra) : "r"(la), "r"(p));
                asm volatile("st.shared::cluster.f32 [%0], %1;"
                             :: "r"(ra), "f"(v) : "memory");
            }
        }
    }
}

// block reduce over 256 threads (8 warps)
__device__ __forceinline__ float bred8(float v, float* red) {
    #pragma unroll
    for (int o = 16; o > 0; o >>= 1) v += __shfl_down_sync(0xffffffffu, v, o);
    const int lane = threadIdx.x & 31, wp = threadIdx.x >> 5;
    if (lane == 0) red[wp] = v;
    __syncthreads();
    if (wp == 0) {
        float s = (lane < 8) ? red[lane] : 0.0f;
        #pragma unroll
        for (int o = 4; o > 0; o >>= 1) s += __shfl_down_sync(0xffffffffu, s, o);
        if (lane == 0) red[0] = s;
    }
    __syncthreads();
    const float s = red[0];
    __syncthreads();
    return s;
}

__device__ __forceinline__ void ln256(const float* __restrict__ hv,
                                      const float* __restrict__ g,
                                      const float* __restrict__ bt,
                                      float* sa, float* red) {
    const int tid = threadIdx.x;
    const float v = hv[tid];
    const float m = bred8(v, red) * (1.0f / (float)HH);
    const float d = v - m;
    const float var = bred8(d * d, red) * (1.0f / (float)HH);
    const float rs = 1.0f / sqrtf(var + 1e-5f);
    sa[tid] = d * rs * g[tid] + bt[tid];
    __syncthreads();
}

// 71-dim LN stats via warp 0
__device__ __forceinline__ void ln71_stats(const float* __restrict__ zv, float* mv) {
    const int lane = threadIdx.x & 31, wp = threadIdx.x >> 5;
    if (wp == 0) {
        const float v0 = zv[lane], v1 = zv[lane + 32];
        const float v2 = (lane < D0 - 64) ? zv[lane + 64] : 0.f;
        float s = v0 + v1 + v2;
        #pragma unroll
        for (int o = 16; o; o >>= 1) s += __shfl_xor_sync(0xffffffffu, s, o);
        const float m = s / (float)D0;
        float q = (v0 - m) * (v0 - m) + (v1 - m) * (v1 - m);
        if (lane < D0 - 64) q += (v2 - m) * (v2 - m);
        #pragma unroll
        for (int o = 16; o; o >>= 1) q += __shfl_xor_sync(0xffffffffu, q, o);
        if (lane == 0) { mv[0] = m; mv[1] = 1.0f / sqrtf(q / (float)D0 + 1e-5f); }
    }
    __syncthreads();
}

// 32 rows of a 256x256 GEMV (this CTA's slice), 4 rows/warp.
// mode 0=plain, 1=gelu, 2=accumulate. Writes into outv[rank*32 .. +31].
__device__ __forceinline__ void gemv_slice(const float* __restrict__ w,
                                           const float* __restrict__ bias,
                                           const float* __restrict__ in,
                                           float* __restrict__ outv,
                                           int rank, int mode) {
    const int lane = threadIdx.x & 31, wp = threadIdx.x >> 5;
    const float4 a0 = ((const float4*)in)[lane];
    const float4 a1 = ((const float4*)in)[lane + 32];
    const int rb = (rank << 5) + (wp << 2);
    float4 x0[4], x1[4];
    #pragma unroll
    for (int r = 0; r < 4; r++) {
        const float4* w4 = (const float4*)w + (size_t)(rb + r) * 64;
        x0[r] = __ldg(&w4[lane]);
        x1[r] = __ldg(&w4[lane + 32]);
    }
    #pragma unroll
    for (int r = 0; r < 4; r++) {
        float s = x0[r].x * a0.x + x0[r].y * a0.y + x0[r].z * a0.z + x0[r].w * a0.w
                + x1[r].x * a1.x + x1[r].y * a1.y + x1[r].z * a1.z + x1[r].w * a1.w;
        #pragma unroll
        for (int o = 16; o; o >>= 1) s += __shfl_xor_sync(0xffffffffu, s, o);
        if (lane == 0) {
            const int row = rb + r;
            const float v = s + __ldg(&bias[row]);
            if (mode == 0) outv[row] = v;
            else if (mode == 1) outv[row] = geluf(v);
            else outv[row] += v;
        }
    }
    __syncthreads();
}

// 16 clusters x 8 CTAs x 256 threads.
__global__ void __launch_bounds__(256) __cluster_dims__(CSZ, 1, 1)
logits_cluster(Ptrs P) {
    const float* x     = P.p[0];  const float* stats = P.p[1];
    const float* ln0_g = P.p[3];  const float* ln0_b = P.p[4];
    const float* r1lg  = P.p[5];  const float* r1lb  = P.p[6];
    const float* r1w1  = P.p[7];  const float* r1b1  = P.p[8];
    const float* r1w2  = P.p[9];  const float* r1b2  = P.p[10];
    const float* r1wp  = P.p[11]; const float* r1bp  = P.p[12];
    const float* r2lg  = P.p[13]; const float* r2lb  = P.p[14];
    const float* r2w1  = P.p[15]; const float* r2b1  = P.p[16];
    const float* r2w2  = P.p[17]; const float* r2b2  = P.p[18];
    const float* alg   = P.p[19]; const float* alb   = P.p[20];
    const float* awin  = P.p[21]; const float* abin  = P.p[22];
    const float* awout = P.p[23]; const float* about_= P.p[24];
    const float* ow    = P.p[25]; const float* ob    = P.p[26];
    const float* fw    = P.p[27]; const float* fb    = P.p[28];

    const int b = blockIdx.x >> 3;
    const int rank = (int)ctarank();
    const int tid = threadIdx.x, lane = tid & 31, wp = tid >> 5;

    __shared__ __align__(16) float z[128], za[128];
    __shared__ __align__(16) float sa[HH], sb[HH], sh[HH], st[HH];
    __shared__ float red[8], mv[2];

    pfr(r1w1, 568);  pfr(r1wp, 568);
    pfr(r1w2, 2048); pfr(r2w1, 2048); pfr(r2w2, 2048);
    pfr(awin + 2 * HH * HH, 2048); pfr(awout, 2048); pfr(ow, 2048);

    // allow the dependent fill kernel to start early (PDL)
    asm volatile("griddepcontrol.launch_dependents;" ::: "memory");

    // prologue (redundant per CTA): z, ln0, rb1-LN
    if (tid < 128) { z[tid] = 0.f; za[tid] = 0.f; }
    __syncthreads();
    if (tid < 64)      z[tid] = x[b * 64 + tid];
    else if (tid < D0) z[tid] = stats[b * 7 + tid - 64];
    __syncthreads();
    ln71_stats(z, mv);
    if (tid < D0) z[tid] = (z[tid] - mv[0]) * mv[1] * ln0_g[tid] + ln0_b[tid];
    __syncthreads();
    ln71_stats(z, mv);
    if (tid < D0) za[tid] = (z[tid] - mv[0]) * mv[1] * r1lg[tid] + r1lb[tid];
    __syncthreads();

    // Stage A: st = gelu(r1w1 @ za + b1)  [256x71], 32 rows/CTA (4/warp)
    {
        const float a0 = za[lane], a1 = za[lane + 32];
        const float a2 = (lane < D0 - 64) ? za[lane + 64] : 0.f;
        #pragma unroll
        for (int r = 0; r < 4; r++) {
            const int row = (rank << 5) + (wp << 2) + r;
            const float* wr = r1w1 + row * D0;
            float s = __ldg(&wr[lane]) * a0 + __ldg(&wr[lane + 32]) * a1;
            if (lane < D0 - 64) s += __ldg(&wr[lane + 64]) * a2;
            #pragma unroll
            for (int o = 16; o; o >>= 1) s += __shfl_xor_sync(0xffffffffu, s, o);
            if (lane == 0) st[row] = geluf(s + __ldg(&r1b1[row]));
        }
    }
    __syncthreads();
    bcast32(st, rank);
    CLUSTER_SYNC();

    // Stage B: sh = r1w2 @ st + r1wp @ z + b2 + bp
    {
        const float4 a0 = ((const float4*)st)[lane];
        const float4 a1 = ((const float4*)st)[lane + 32];
        const float z0 = z[lane], z1 = z[lane + 32];
        const float z2 = (lane < D0 - 64) ? z[lane + 64] : 0.f;
        #pragma unroll
        for (int r = 0; r < 4; r++) {
            const int row = (rank << 5) + (wp << 2) + r;
            const float* wr = r1wp + row * D0;
            float sp = __ldg(&wr[lane]) * z0 + __ldg(&wr[lane + 32]) * z1;
            if (lane < D0 - 64) sp += __ldg(&wr[lane + 64]) * z2;
            const float4* w4 = (const float4*)r1w2 + (size_t)row * 64;
            const float4 x0 = __ldg(&w4[lane]);
            const float4 x1 = __ldg(&w4[lane + 32]);
            float s = x0.x * a0.x + x0.y * a0.y + x0.z * a0.z + x0.w * a0.w
                    + x1.x * a1.x + x1.y * a1.y + x1.z * a1.z + x1.w * a1.w + sp;
            #pragma unroll
            for (int o = 16; o; o >>= 1) s += __shfl_xor_sync(0xffffffffu, s, o);
            if (lane == 0) sh[row] = s + __ldg(&r1b2[row]) + __ldg(&r1bp[row]);
        }
    }
    __syncthreads();
    bcast32(sh, rank);
    CLUSTER_SYNC();

    // rb2
    ln256(sh, r2lg, r2lb, sa, red);
    gemv_slice(r2w1, r2b1, sa, st, rank, 1);
    bcast32(st, rank);
    CLUSTER_SYNC();
    gemv_slice(r2w2, r2b2, st, sh, rank, 2);
    bcast32(sh, rank);
    CLUSTER_SYNC();

    // attention (tokens identical -> o == v)
    ln256(sh, alg, alb, sa, red);
    gemv_slice(awin + 2 * HH * HH, abin + 2 * HH, sa, st, rank, 0);
    bcast32(st, rank);
    CLUSTER_SYNC();
    gemv_slice(awout, about_, st, sb, rank, 0);
    bcast32(sb, rank);
    CLUSTER_SYNC();
    gemv_slice(ow, ob, sb, st, rank, 0);
    bcast32(st, rank);
    CLUSTER_SYNC();

    // final logits on rank 0 (st fully assembled)
    if (rank == 0) {
        const float hv = st[tid];
        const float f0 = __ldg(&fw[tid]) + __ldg(&fw[HH + tid]);
        const float f1 = __ldg(&fw[2 * HH + tid]) + __ldg(&fw[3 * HH + tid]);
        const float l0 = bred8(f0 * hv, red) + fb[0];
        const float l1 = bred8(f1 * hv, red) + fb[1];
        if (tid == 0) g_c[b] = expf(l1 - l0);
    }
}

// ---------- fill: PDL two-phase (logs before grid-dep wait) ----------
__device__ __forceinline__ float decide(float w0, float w1, float cb,
                                        const float2* __restrict__ ub, int p) {
    const float cw0 = cb * w0;
    const float d = w1 - cw0;
    const float margin = 3e-6f * (fabsf(w1) + fabsf(cw0)) + 2e-7f;
    if (fabsf(d) > margin) return d >= 0.f ? 1.0f : 0.0f;
    const float2 uu = __ldg(&ub[p]);
    const float e0 = 1e-10f - logf(uu.x + 1e-10f);
    const float e1 = 1e-10f - logf(uu.y + 1e-10f);
    return (e1 >= cb * e0) ? 1.0f : 0.0f;
}

__global__ void __launch_bounds__(256) fill_adj_kernel(const float2* __restrict__ u2,
                                                       float* __restrict__ out) {
    const int b = blockIdx.y;
    const int tl = blockIdx.x;
    int r = (int)((33.0f - sqrtf(1089.0f - 8.0f * (float)tl)) * 0.5f);
    while (r > 0 && r * (33 - r) / 2 > tl) r--;
    while ((r + 1) * (33 - (r + 1)) / 2 <= tl) r++;
    const int c = r + (tl - r * (33 - r) / 2);
    const int i0 = r << 6, j0 = c << 6;
    const bool diag = (i0 == j0);

    const float2* __restrict__ ub = u2 + (size_t)b * PP;
    float* __restrict__ obp = out + (size_t)b * NN * NN;
    __shared__ float sw0[64][65];   // w0; later overwritten with e (row-major [i][col])
    __shared__ float sw1[64][65];   // w1

    const int tx = threadIdx.x;     // 0..15
    const int ty = threadIdx.y;     // 0..15

    // ---- phase A: u loads + logs (independent of g_c) ----
    #pragma unroll
    for (int rr = 0; rr < 4; rr++) {
        const int ti = ty + (rr << 4);
        const int i = i0 + ti;
        const int rowbase = (i * (2047 - i)) / 2 - i - 1 + j0;
        const int p0 = rowbase + 4 * tx;
        if (!diag) {
            float ux[4], uy[4];
            if (!(rowbase & 1)) {
                const float4* u4 = (const float4*)ub;
                const float4 A  = __ldg(&u4[p0 >> 1]);
                const float4 Bq = __ldg(&u4[(p0 >> 1) + 1]);
                ux[0] = A.x;  uy[0] = A.y;  ux[1] = A.z;  uy[1] = A.w;
                ux[2] = Bq.x; uy[2] = Bq.y; ux[3] = Bq.z; uy[3] = Bq.w;
            } else {
                #pragma unroll
                for (int k = 0; k < 4; k++) {
                    const float2 t = __ldg(&ub[p0 + k]);
                    ux[k] = t.x; uy[k] = t.y;
                }
            }
            #pragma unroll
            for (int k = 0; k < 4; k++) {
                sw0[ti][4 * tx + k] = 1e-10f - __logf(ux[k] + 1e-10f);
                sw1[ti][4 * tx + k] = 1e-10f - __logf(uy[k] + 1e-10f);
            }
        } else {
            #pragma unroll
            for (int k = 0; k < 4; k++) {
                const int col = 4 * tx + k;
                float w0v = 1.f, w1v = -1.f;   // sentinel -> e = 0
                if (col > ti) {
                    const float2 t = __ldg(&ub[rowbase + col]);
                    w0v = 1e-10f - __logf(t.x + 1e-10f);
                    w1v = 1e-10f - __logf(t.y + 1e-10f);
                }
                sw0[ti][col] = w0v;
                sw1[ti][col] = w1v;
            }
        }
    }

    // ---- wait for logits grid (hardware PDL dependency) ----
    asm volatile("griddepcontrol.wait;" ::: "memory");
    const float cb = g_c[b];

    // ---- phase B: decide, write upper, store e in place over sw0 ----
    #pragma unroll
    for (int rr = 0; rr < 4; rr++) {
        const int ti = ty + (rr << 4);
        const int i = i0 + ti;
        const int rowbase = (i * (2047 - i)) / 2 - i - 1 + j0;
        float4 ev;
        float* e4 = (float*)&ev;
        #pragma unroll
        for (int k = 0; k < 4; k++) {
            const int col = 4 * tx + k;
            e4[k] = decide(sw0[ti][col], sw1[ti][col], cb, ub, rowbase + col);
        }
        if (!diag) {
            *(float4*)&obp[(size_t)i * NN + j0 + 4 * tx] = ev;
        } else {
            #pragma unroll
            for (int k = 0; k < 4; k++) {
                const int col = 4 * tx + k;
                if (col >= ti) obp[(size_t)i * NN + j0 + col] = e4[k];  // diag -> 0
            }
        }
        #pragma unroll
        for (int k = 0; k < 4; k++) sw0[ti][4 * tx + k] = e4[k];
    }
    __syncthreads();

    // ---- phase C: lower triangle from transposed read of sw0 ----
    #pragma unroll
    for (int rr = 0; rr < 4; rr++) {
        const int tj = ty + (rr << 4);
        if (!diag) {
            float4 f;
            f.x = sw0[4 * tx + 0][tj];
            f.y = sw0[4 * tx + 1][tj];
            f.z = sw0[4 * tx + 2][tj];
            f.w = sw0[4 * tx + 3][tj];
            *(float4*)&obp[(size_t)(j0 + tj) * NN + i0 + 4 * tx] = f;
        } else {
            #pragma unroll
            for (int k = 0; k < 4; k++) {
                const int col = 4 * tx + k;
                if (col < tj) obp[(size_t)(j0 + tj) * NN + i0 + col] = sw0[col][tj];
            }
        }
    }
}

extern "C" void kernel_launch(void* const* d_in, const int* in_sizes, int n_in,
                              void* d_out, int out_size) {
    Ptrs P;
    for (int i = 0; i < 30; i++) P.p[i] = (const float*)d_in[i];

    logits_cluster<<<BB * CSZ, 256>>>(P);

    // fill with programmatic dependent launch: starts while logits runs,
    // griddepcontrol.wait inside guarantees g_c visibility.
    cudaLaunchConfig_t cfg = {};
    cfg.gridDim = dim3(NTILE, BB);
    cfg.blockDim = dim3(16, 16);
    cfg.dynamicSmemBytes = 0;
    cfg.stream = 0;
    cudaLaunchAttribute attrs[1];
    attrs[0].id = cudaLaunchAttributeProgrammaticStreamSerialization;
    attrs[0].val.programmaticStreamSerializationAllowed = 1;
    cfg.attrs = attrs;
    cfg.numAttrs = 1;
    cudaLaunchKernelEx(&cfg, fill_adj_kernel, (const float2*)d_in[2], (float*)d_out);
}

// round 16
// speedup vs baseline: 1.0797x; 1.0409x over previous
#include <cuda_runtime.h>
#include <cstdint>
#include <stdint.h>
#include <math.h>

#define NN 1024
#define HH 256
#define D0 71
#define BB 16
#define PP 523776   // NN*(NN-1)/2
#define NTILE 136
#define CSZ 8       // cluster size (CTAs per batch)

__device__ float g_c[BB];

struct Ptrs { const float* p[30]; };

__device__ __forceinline__ float geluf(float x) {
    return 0.5f * x * (1.0f + erff(x * 0.70710678118654752440f));
}

__device__ __forceinline__ unsigned s2u(const void* p) {
    unsigned a;
    asm("{ .reg .u64 t; cvta.to.shared.u64 t, %1; cvt.u32.u64 %0, t; }"
        : "=r"(a) : "l"(p));
    return a;
}

__device__ __forceinline__ unsigned ctarank() {
    unsigned r; asm("mov.u32 %0, %%cluster_ctarank;" : "=r"(r)); return r;
}

#define CLUSTER_SYNC() do { \
    asm volatile("barrier.cluster.arrive.aligned;" ::: "memory"); \
    asm volatile("barrier.cluster.wait.aligned;"   ::: "memory"); \
} while (0)

__device__ __forceinline__ void l2pf(const void* p) {
    asm volatile("prefetch.global.L2 [%0];" :: "l"(p));
}
// partition prefetch of nlines 128B lines across the 128 logits blocks
__device__ __forceinline__ void pfr(const float* w, int nlines) {
    const int l = blockIdx.x + (threadIdx.x << 7);
    if (l < nlines) l2pf((const char*)w + (size_t)l * 128);
}

// broadcast this CTA's 32-row slice of arr[256] to the other 7 cluster CTAs
__device__ __forceinline__ void bcast32(float* arr, int rank) {
    const int tid = threadIdx.x;
    if (tid < 32) {
        const int idx = (rank << 5) + tid;
        const float v = arr[idx];
        const unsigned la = s2u(&arr[idx]);
        #pragma unroll
        for (int p = 0; p < CSZ; p++) {
            if (p != rank) {
                unsigned ra;
                asm volatile("mapa.shared::cluster.u32 %0, %1, %2;"
                             : "=r"(ra) : "r"(la), "r"(p));
                asm volatile("st.shared::cluster.f32 [%0], %1;"
                             :: "r"(ra), "f"(v) : "memory");
            }
        }
    }
}

// block reduce over 256 threads (8 warps)
__device__ __forceinline__ float bred8(float v, float* red) {
    #pragma unroll
    for (int o = 16; o > 0; o >>= 1) v += __shfl_down_sync(0xffffffffu, v, o);
    const int lane = threadIdx.x & 31, wp = threadIdx.x >> 5;
    if (lane == 0) red[wp] = v;
    __syncthreads();
    if (wp == 0) {
        float s = (lane < 8) ? red[lane] : 0.0f;
        #pragma unroll
        for (int o = 4; o > 0; o >>= 1) s += __shfl_down_sync(0xffffffffu, s, o);
        if (lane == 0) red[0] = s;
    }
    __syncthreads();
    const float s = red[0];
    __syncthreads();
    return s;
}

__device__ __forceinline__ void ln256(const float* __restrict__ hv,
                                      const float* __restrict__ g,
                                      const float* __restrict__ bt,
                                      float* sa, float* red) {
    const int tid = threadIdx.x;
    const float v = hv[tid];
    const float m = bred8(v, red) * (1.0f / (float)HH);
    const float d = v - m;
    const float var = bred8(d * d, red) * (1.0f / (float)HH);
    const float rs = 1.0f / sqrtf(var + 1e-5f);
    sa[tid] = d * rs * g[tid] + bt[tid];
    __syncthreads();
}

// 71-dim LN stats via warp 0
__device__ __forceinline__ void ln71_stats(const float* __restrict__ zv, float* mv) {
    const int lane = threadIdx.x & 31, wp = threadIdx.x >> 5;
    if (wp == 0) {
        const float v0 = zv[lane], v1 = zv[lane + 32];
        const float v2 = (lane < D0 - 64) ? zv[lane + 64] : 0.f;
        float s = v0 + v1 + v2;
        #pragma unroll
        for (int o = 16; o; o >>= 1) s += __shfl_xor_sync(0xffffffffu, s, o);
        const float m = s / (float)D0;
        float q = (v0 - m) * (v0 - m) + (v1 - m) * (v1 - m);
        if (lane < D0 - 64) q += (v2 - m) * (v2 - m);
        #pragma unroll
        for (int o = 16; o; o >>= 1) q += __shfl_xor_sync(0xffffffffu, q, o);
        if (lane == 0) { mv[0] = m; mv[1] = 1.0f / sqrtf(q / (float)D0 + 1e-5f); }
    }
    __syncthreads();
}

// 32 rows of a 256x256 GEMV (this CTA's slice), 4 rows/warp.
// mode 0=plain, 1=gelu, 2=accumulate. Writes into outv[rank*32 .. +31].
__device__ __forceinline__ void gemv_slice(const float* __restrict__ w,
                                           const float* __restrict__ bias,
                                           const float* __restrict__ in,
                                           float* __restrict__ outv,
                                           int rank, int mode) {
    const int lane = threadIdx.x & 31, wp = threadIdx.x >> 5;
    const float4 a0 = ((const float4*)in)[lane];
    const float4 a1 = ((const float4*)in)[lane + 32];
    const int rb = (rank << 5) + (wp << 2);
    float4 x0[4], x1[4];
    #pragma unroll
    for (int r = 0; r < 4; r++) {
        const float4* w4 = (const float4*)w + (size_t)(rb + r) * 64;
        x0[r] = __ldg(&w4[lane]);
        x1[r] = __ldg(&w4[lane + 32]);
    }
    #pragma unroll
    for (int r = 0; r < 4; r++) {
        float s = x0[r].x * a0.x + x0[r].y * a0.y + x0[r].z * a0.z + x0[r].w * a0.w
                + x1[r].x * a1.x + x1[r].y * a1.y + x1[r].z * a1.z + x1[r].w * a1.w;
        #pragma unroll
        for (int o = 16; o; o >>= 1) s += __shfl_xor_sync(0xffffffffu, s, o);
        if (lane == 0) {
            const int row = rb + r;
            const float v = s + __ldg(&bias[row]);
            if (mode == 0) outv[row] = v;
            else if (mode == 1) outv[row] = geluf(v);
            else outv[row] += v;
        }
    }
    __syncthreads();
}

// 16 clusters x 8 CTAs x 256 threads.
__global__ void __launch_bounds__(256) __cluster_dims__(CSZ, 1, 1)
logits_cluster(Ptrs P) {
    const float* x     = P.p[0];  const float* stats = P.p[1];
    const float* ln0_g = P.p[3];  const float* ln0_b = P.p[4];
    const float* r1lg  = P.p[5];  const float* r1lb  = P.p[6];
    const float* r1w1  = P.p[7];  const float* r1b1  = P.p[8];
    const float* r1w2  = P.p[9];  const float* r1b2  = P.p[10];
    const float* r1wp  = P.p[11]; const float* r1bp  = P.p[12];
    const float* r2lg  = P.p[13]; const float* r2lb  = P.p[14];
    const float* r2w1  = P.p[15]; const float* r2b1  = P.p[16];
    const float* r2w2  = P.p[17]; const float* r2b2  = P.p[18];
    const float* alg   = P.p[19]; const float* alb   = P.p[20];
    const float* awin  = P.p[21]; const float* abin  = P.p[22];
    const float* awout = P.p[23]; const float* about_= P.p[24];
    const float* ow    = P.p[25]; const float* ob    = P.p[26];
    const float* fw    = P.p[27]; const float* fb    = P.p[28];

    const int b = blockIdx.x >> 3;
    const int rank = (int)ctarank();
    const int tid = threadIdx.x, lane = tid & 31, wp = tid >> 5;

    __shared__ __align__(16) float z[128], za[128];
    __shared__ __align__(16) float sa[HH], sb[HH], sh[HH], st[HH];
    __shared__ float red[8], mv[2];

    pfr(r1w1, 568);  pfr(r1wp, 568);
    pfr(r1w2, 2048); pfr(r2w1, 2048); pfr(r2w2, 2048);
    pfr(awin + 2 * HH * HH, 2048); pfr(awout, 2048); pfr(ow, 2048);

    // prologue (redundant per CTA): z, ln0, rb1-LN
    if (tid < 128) { z[tid] = 0.f; za[tid] = 0.f; }
    __syncthreads();
    if (tid < 64)      z[tid] = x[b * 64 + tid];
    else if (tid < D0) z[tid] = stats[b * 7 + tid - 64];
    __syncthreads();
    ln71_stats(z, mv);
    if (tid < D0) z[tid] = (z[tid] - mv[0]) * mv[1] * ln0_g[tid] + ln0_b[tid];
    __syncthreads();
    ln71_stats(z, mv);
    if (tid < D0) za[tid] = (z[tid] - mv[0]) * mv[1] * r1lg[tid] + r1lb[tid];
    __syncthreads();

    // Stage A: st = gelu(r1w1 @ za + b1)  [256x71], 32 rows/CTA (4/warp)
    {
        const float a0 = za[lane], a1 = za[lane + 32];
        const float a2 = (lane < D0 - 64) ? za[lane + 64] : 0.f;
        #pragma unroll
        for (int r = 0; r < 4; r++) {
            const int row = (rank << 5) + (wp << 2) + r;
            const float* wr = r1w1 + row * D0;
            float s = __ldg(&wr[lane]) * a0 + __ldg(&wr[lane + 32]) * a1;
            if (lane < D0 - 64) s += __ldg(&wr[lane + 64]) * a2;
            #pragma unroll
            for (int o = 16; o; o >>= 1) s += __shfl_xor_sync(0xffffffffu, s, o);
            if (lane == 0) st[row] = geluf(s + __ldg(&r1b1[row]));
        }
    }
    __syncthreads();
    bcast32(st, rank);
    CLUSTER_SYNC();

    // Stage B: sh = r1w2 @ st + r1wp @ z + b2 + bp
    {
        const float4 a0 = ((const float4*)st)[lane];
        const float4 a1 = ((const float4*)st)[lane + 32];
        const float z0 = z[lane], z1 = z[lane + 32];
        const float z2 = (lane < D0 - 64) ? z[lane + 64] : 0.f;
        #pragma unroll
        for (int r = 0; r < 4; r++) {
            const int row = (rank << 5) + (wp << 2) + r;
            const float* wr = r1wp + row * D0;
            float sp = __ldg(&wr[lane]) * z0 + __ldg(&wr[lane + 32]) * z1;
            if (lane < D0 - 64) sp += __ldg(&wr[lane + 64]) * z2;
            const float4* w4 = (const float4*)r1w2 + (size_t)row * 64;
            const float4 x0 = __ldg(&w4[lane]);
            const float4 x1 = __ldg(&w4[lane + 32]);
            float s = x0.x * a0.x + x0.y * a0.y + x0.z * a0.z + x0.w * a0.w
                    + x1.x * a1.x + x1.y * a1.y + x1.z * a1.z + x1.w * a1.w + sp;
            #pragma unroll
            for (int o = 16; o; o >>= 1) s += __shfl_xor_sync(0xffffffffu, s, o);
            if (lane == 0) sh[row] = s + __ldg(&r1b2[row]) + __ldg(&r1bp[row]);
        }
    }
    __syncthreads();
    bcast32(sh, rank);
    CLUSTER_SYNC();

    // rb2
    ln256(sh, r2lg, r2lb, sa, red);
    gemv_slice(r2w1, r2b1, sa, st, rank, 1);
    bcast32(st, rank);
    CLUSTER_SYNC();
    gemv_slice(r2w2, r2b2, st, sh, rank, 2);
    bcast32(sh, rank);
    CLUSTER_SYNC();

    // attention (tokens identical -> o == v)
    ln256(sh, alg, alb, sa, red);
    gemv_slice(awin + 2 * HH * HH, abin + 2 * HH, sa, st, rank, 0);
    bcast32(st, rank);
    CLUSTER_SYNC();
    gemv_slice(awout, about_, st, sb, rank, 0);
    bcast32(sb, rank);
    CLUSTER_SYNC();
    gemv_slice(ow, ob, sb, st, rank, 0);
    bcast32(st, rank);
    CLUSTER_SYNC();

    // final logits on rank 0 (st fully assembled)
    if (rank == 0) {
        const float hv = st[tid];
        const float f0 = __ldg(&fw[tid]) + __ldg(&fw[HH + tid]);
        const float f1 = __ldg(&fw[2 * HH + tid]) + __ldg(&fw[3 * HH + tid]);
        const float l0 = bred8(f0 * hv, red) + fb[0];
        const float l1 = bred8(f1 * hv, red) + fb[1];
        if (tid == 0) g_c[b] = expf(l1 - l0);
    }
}

// ---------- fill (R6 structure; output via streaming stores __stcs) ----------
__device__ __forceinline__ float edge_val(float ux, float uy, float cb) {
    const float w0 = 1e-10f - __logf(ux + 1e-10f);
    const float w1 = 1e-10f - __logf(uy + 1e-10f);
    const float cw0 = cb * w0;
    const float d = w1 - cw0;
    const float margin = 3e-6f * (fabsf(w1) + fabsf(cw0)) + 2e-7f;
    if (fabsf(d) > margin) return d >= 0.f ? 1.0f : 0.0f;
    const float e0 = 1e-10f - logf(ux + 1e-10f);
    const float e1 = 1e-10f - logf(uy + 1e-10f);
    return (e1 >= cb * e0) ? 1.0f : 0.0f;
}

__global__ void __launch_bounds__(256) fill_adj_kernel(const float2* __restrict__ u2,
                                                       float* __restrict__ out) {
    const int b = blockIdx.y;
    const int tl = blockIdx.x;
    int r = (int)((33.0f - sqrtf(1089.0f - 8.0f * (float)tl)) * 0.5f);
    while (r > 0 && r * (33 - r) / 2 > tl) r--;
    while ((r + 1) * (33 - (r + 1)) / 2 <= tl) r++;
    const int c = r + (tl - r * (33 - r) / 2);
    const int i0 = r << 6, j0 = c << 6;

    const float cb = g_c[b];
    const float2* __restrict__ ub = u2 + (size_t)b * PP;
    float* __restrict__ obp = out + (size_t)b * NN * NN;
    __shared__ float tile[64][65];   // stored TRANSPOSED: tile[jloc][iloc]

    const int tx = threadIdx.x;      // 0..15
    const int ty = threadIdx.y;      // 0..15

    if (i0 != j0) {
        #pragma unroll
        for (int rr = 0; rr < 4; rr++) {
            const int ti = ty + (rr << 4);
            const int i = i0 + ti;
            const int rowbase = (i * (2047 - i)) / 2 - i - 1 + j0;
            const int p0 = rowbase + 4 * tx;
            float4 ev;
            if (!(rowbase & 1)) {
                const float4* u4 = (const float4*)ub;
                const float4 A = __ldg(&u4[p0 >> 1]);
                const float4 Bq = __ldg(&u4[(p0 >> 1) + 1]);
                ev.x = edge_val(A.x,  A.y,  cb);
                ev.y = edge_val(A.z,  A.w,  cb);
                ev.z = edge_val(Bq.x, Bq.y, cb);
                ev.w = edge_val(Bq.z, Bq.w, cb);
            } else {
                const float2 a = __ldg(&ub[p0]);
                const float2 bq = __ldg(&ub[p0 + 1]);
                const float2 cq = __ldg(&ub[p0 + 2]);
                const float2 dq = __ldg(&ub[p0 + 3]);
                ev.x = edge_val(a.x,  a.y,  cb);
                ev.y = edge_val(bq.x, bq.y, cb);
                ev.z = edge_val(cq.x, cq.y, cb);
                ev.w = edge_val(dq.x, dq.y, cb);
            }
            __stcs((float4*)&obp[(size_t)i * NN + j0 + 4 * tx], ev);  // streaming store
            tile[4 * tx + 0][ti] = ev.x;
            tile[4 * tx + 1][ti] = ev.y;
            tile[4 * tx + 2][ti] = ev.z;
            tile[4 * tx + 3][ti] = ev.w;
        }
        __syncthreads();
        #pragma unroll
        for (int rr = 0; rr < 4; rr++) {
            const int tj = ty + (rr << 4);
            float4 f;
            f.x = tile[tj][4 * tx + 0];
            f.y = tile[tj][4 * tx + 1];
            f.z = tile[tj][4 * tx + 2];
            f.w = tile[tj][4 * tx + 3];
            __stcs((float4*)&obp[(size_t)(j0 + tj) * NN + i0 + 4 * tx], f);
        }
    } else {
        #pragma unroll
        for (int rr = 0; rr < 4; rr++) {
            const int ti = ty + (rr << 4);
            const int i = i0 + ti;
            const int rowbase = (i * (2047 - i)) / 2 - i - 1 + j0;
            #pragma unroll
            for (int k = 0; k < 4; k++) {
                const int col = 4 * tx + k;
                float e = 0.f;
                if (col > ti) {
                    const float2 uu = __ldg(&ub[rowbase + col]);
                    e = edge_val(uu.x, uu.y, cb);
                }
                tile[col][ti] = e;
                if (col >= ti) __stcs(&obp[(size_t)i * NN + j0 + col], e);
            }
        }
        __syncthreads();
        #pragma unroll
        for (int rr = 0; rr < 4; rr++) {
            const int tj = ty + (rr << 4);
            #pragma unroll
            for (int k = 0; k < 4; k++) {
                const int col = 4 * tx + k;
                if (col < tj) __stcs(&obp[(size_t)(j0 + tj) * NN + i0 + col], tile[tj][col]);
            }
        }
    }
}

extern "C" void kernel_launch(void* const* d_in, const int* in_sizes, int n_in,
                              void* d_out, int out_size) {
    Ptrs P;
    for (int i = 0; i < 30; i++) P.p[i] = (const float*)d_in[i];

    logits_cluster<<<BB * CSZ, 256>>>(P);

    dim3 grid(NTILE, BB), blk(16, 16);
    fill_adj_kernel<<<grid, blk>>>((const float2*)d_in[2], (float*)d_out);
}

// round 17
// speedup vs baseline: 1.0805x; 1.0007x over previous
#include <cuda_runtime.h>
#include <cstdint>
#include <stdint.h>
#include <math.h>

#define NN 1024
#define HH 256
#define D0 71
#define BB 16
#define PP 523776   // NN*(NN-1)/2
#define NTILE 136
#define CSZ 8       // cluster size (CTAs per batch)

__device__ float g_c[BB];

struct Ptrs { const float* p[30]; };

__device__ __forceinline__ float geluf(float x) {
    return 0.5f * x * (1.0f + erff(x * 0.70710678118654752440f));
}

__device__ __forceinline__ unsigned s2u(const void* p) {
    unsigned a;
    asm("{ .reg .u64 t; cvta.to.shared.u64 t, %1; cvt.u32.u64 %0, t; }"
        : "=r"(a) : "l"(p));
    return a;
}

__device__ __forceinline__ unsigned ctarank() {
    unsigned r; asm("mov.u32 %0, %%cluster_ctarank;" : "=r"(r)); return r;
}

#define CLUSTER_SYNC() do { \
    asm volatile("barrier.cluster.arrive.aligned;" ::: "memory"); \
    asm volatile("barrier.cluster.wait.aligned;"   ::: "memory"); \
} while (0)

__device__ __forceinline__ void l2pf(const void* p) {
    asm volatile("prefetch.global.L2 [%0];" :: "l"(p));
}
// partition prefetch of nlines 128B lines across the 128 logits blocks
__device__ __forceinline__ void pfr(const float* w, int nlines) {
    const int l = blockIdx.x + (threadIdx.x << 7);
    if (l < nlines) l2pf((const char*)w + (size_t)l * 128);
}

// broadcast this CTA's 32-row slice of arr[256] to the other 7 cluster CTAs
__device__ __forceinline__ void bcast32(float* arr, int rank) {
    const int tid = threadIdx.x;
    if (tid < 32) {
        const int idx = (rank << 5) + tid;
        const float v = arr[idx];
        const unsigned la = s2u(&arr[idx]);
        #pragma unroll
        for (int p = 0; p < CSZ; p++) {
            if (p != rank) {
                unsigned ra;
                asm volatile("mapa.shared::cluster.u32 %0, %1, %2;"
                             : "=r"(ra) : "r"(la), "r"(p));
                asm volatile("st.shared::cluster.f32 [%0], %1;"
                             :: "r"(ra), "f"(v) : "memory");
            }
        }
    }
}

// block reduce over 256 threads (8 warps)
__device__ __forceinline__ float bred8(float v, float* red) {
    #pragma unroll
    for (int o = 16; o > 0; o >>= 1) v += __shfl_down_sync(0xffffffffu, v, o);
    const int lane = threadIdx.x & 31, wp = threadIdx.x >> 5;
    if (lane == 0) red[wp] = v;
    __syncthreads();
    if (wp == 0) {
        float s = (lane < 8) ? red[lane] : 0.0f;
        #pragma unroll
        for (int o = 4; o > 0; o >>= 1) s += __shfl_down_sync(0xffffffffu, s, o);
        if (lane == 0) red[0] = s;
    }
    __syncthreads();
    const float s = red[0];
    __syncthreads();
    return s;
}

__device__ __forceinline__ void ln256(const float* __restrict__ hv,
                                      const float* __restrict__ g,
                                      const float* __restrict__ bt,
                                      float* sa, float* red) {
    const int tid = threadIdx.x;
    const float v = hv[tid];
    const float m = bred8(v, red) * (1.0f / (float)HH);
    const float d = v - m;
    const float var = bred8(d * d, red) * (1.0f / (float)HH);
    const float rs = 1.0f / sqrtf(var + 1e-5f);
    sa[tid] = d * rs * g[tid] + bt[tid];
    __syncthreads();
}

// 71-dim LN stats via warp 0
__device__ __forceinline__ void ln71_stats(const float* __restrict__ zv, float* mv) {
    const int lane = threadIdx.x & 31, wp = threadIdx.x >> 5;
    if (wp == 0) {
        const float v0 = zv[lane], v1 = zv[lane + 32];
        const float v2 = (lane < D0 - 64) ? zv[lane + 64] : 0.f;
        float s = v0 + v1 + v2;
        #pragma unroll
        for (int o = 16; o; o >>= 1) s += __shfl_xor_sync(0xffffffffu, s, o);
        const float m = s / (float)D0;
        float q = (v0 - m) * (v0 - m) + (v1 - m) * (v1 - m);
        if (lane < D0 - 64) q += (v2 - m) * (v2 - m);
        #pragma unroll
        for (int o = 16; o; o >>= 1) q += __shfl_xor_sync(0xffffffffu, q, o);
        if (lane == 0) { mv[0] = m; mv[1] = 1.0f / sqrtf(q / (float)D0 + 1e-5f); }
    }
    __syncthreads();
}

// 32 rows of a 256x256 GEMV (this CTA's slice), 4 rows/warp.
// mode 0=plain, 1=gelu, 2=accumulate. Writes into outv[rank*32 .. +31].
__device__ __forceinline__ void gemv_slice(const float* __restrict__ w,
                                           const float* __restrict__ bias,
                                           const float* __restrict__ in,
                                           float* __restrict__ outv,
                                           int rank, int mode) {
    const int lane = threadIdx.x & 31, wp = threadIdx.x >> 5;
    const float4 a0 = ((const float4*)in)[lane];
    const float4 a1 = ((const float4*)in)[lane + 32];
    const int rb = (rank << 5) + (wp << 2);
    float4 x0[4], x1[4];
    #pragma unroll
    for (int r = 0; r < 4; r++) {
        const float4* w4 = (const float4*)w + (size_t)(rb + r) * 64;
        x0[r] = __ldg(&w4[lane]);
        x1[r] = __ldg(&w4[lane + 32]);
    }
    #pragma unroll
    for (int r = 0; r < 4; r++) {
        float s = x0[r].x * a0.x + x0[r].y * a0.y + x0[r].z * a0.z + x0[r].w * a0.w
                + x1[r].x * a1.x + x1[r].y * a1.y + x1[r].z * a1.z + x1[r].w * a1.w;
        #pragma unroll
        for (int o = 16; o; o >>= 1) s += __shfl_xor_sync(0xffffffffu, s, o);
        if (lane == 0) {
            const int row = rb + r;
            const float v = s + __ldg(&bias[row]);
            if (mode == 0) outv[row] = v;
            else if (mode == 1) outv[row] = geluf(v);
            else outv[row] += v;
        }
    }
    __syncthreads();
}

// 16 clusters x 8 CTAs x 256 threads.
__global__ void __launch_bounds__(256) __cluster_dims__(CSZ, 1, 1)
logits_cluster(Ptrs P) {
    const float* x     = P.p[0];  const float* stats = P.p[1];
    const float* ln0_g = P.p[3];  const float* ln0_b = P.p[4];
    const float* r1lg  = P.p[5];  const float* r1lb  = P.p[6];
    const float* r1w1  = P.p[7];  const float* r1b1  = P.p[8];
    const float* r1w2  = P.p[9];  const float* r1b2  = P.p[10];
    const float* r1wp  = P.p[11]; const float* r1bp  = P.p[12];
    const float* r2lg  = P.p[13]; const float* r2lb  = P.p[14];
    const float* r2w1  = P.p[15]; const float* r2b1  = P.p[16];
    const float* r2w2  = P.p[17]; const float* r2b2  = P.p[18];
    const float* alg   = P.p[19]; const float* alb   = P.p[20];
    const float* awin  = P.p[21]; const float* abin  = P.p[22];
    const float* awout = P.p[23]; const float* about_= P.p[24];
    const float* ow    = P.p[25]; const float* ob    = P.p[26];
    const float* fw    = P.p[27]; const float* fb    = P.p[28];

    const int b = blockIdx.x >> 3;
    const int rank = (int)ctarank();
    const int tid = threadIdx.x, lane = tid & 31, wp = tid >> 5;

    __shared__ __align__(16) float z[128], za[128];
    __shared__ __align__(16) float sa[HH], sb[HH], sh[HH], st[HH];
    __shared__ float red[8], mv[2];

    pfr(r1w1, 568);  pfr(r1wp, 568);
    pfr(r1w2, 2048); pfr(r2w1, 2048); pfr(r2w2, 2048);
    pfr(awin + 2 * HH * HH, 2048); pfr(awout, 2048); pfr(ow, 2048);

    // prologue (redundant per CTA): z, ln0, rb1-LN
    if (tid < 128) { z[tid] = 0.f; za[tid] = 0.f; }
    __syncthreads();
    if (tid < 64)      z[tid] = x[b * 64 + tid];
    else if (tid < D0) z[tid] = stats[b * 7 + tid - 64];
    __syncthreads();
    ln71_stats(z, mv);
    if (tid < D0) z[tid] = (z[tid] - mv[0]) * mv[1] * ln0_g[tid] + ln0_b[tid];
    __syncthreads();
    ln71_stats(z, mv);
    if (tid < D0) za[tid] = (z[tid] - mv[0]) * mv[1] * r1lg[tid] + r1lb[tid];
    __syncthreads();

    // Stage A: st = gelu(r1w1 @ za + b1)  [256x71], 32 rows/CTA (4/warp)
    {
        const float a0 = za[lane], a1 = za[lane + 32];
        const float a2 = (lane < D0 - 64) ? za[lane + 64] : 0.f;
        #pragma unroll
        for (int r = 0; r < 4; r++) {
            const int row = (rank << 5) + (wp << 2) + r;
            const float* wr = r1w1 + row * D0;
            float s = __ldg(&wr[lane]) * a0 + __ldg(&wr[lane + 32]) * a1;
            if (lane < D0 - 64) s += __ldg(&wr[lane + 64]) * a2;
            #pragma unroll
            for (int o = 16; o; o >>= 1) s += __shfl_xor_sync(0xffffffffu, s, o);
            if (lane == 0) st[row] = geluf(s + __ldg(&r1b1[row]));
        }
    }
    __syncthreads();
    bcast32(st, rank);
    CLUSTER_SYNC();

    // Stage B: sh = r1w2 @ st + r1wp @ z + b2 + bp
    {
        const float4 a0 = ((const float4*)st)[lane];
        const float4 a1 = ((const float4*)st)[lane + 32];
        const float z0 = z[lane], z1 = z[lane + 32];
        const float z2 = (lane < D0 - 64) ? z[lane + 64] : 0.f;
        #pragma unroll
        for (int r = 0; r < 4; r++) {
            const int row = (rank << 5) + (wp << 2) + r;
            const float* wr = r1wp + row * D0;
            float sp = __ldg(&wr[lane]) * z0 + __ldg(&wr[lane + 32]) * z1;
            if (lane < D0 - 64) sp += __ldg(&wr[lane + 64]) * z2;
            const float4* w4 = (const float4*)r1w2 + (size_t)row * 64;
            const float4 x0 = __ldg(&w4[lane]);
            const float4 x1 = __ldg(&w4[lane + 32]);
            float s = x0.x * a0.x + x0.y * a0.y + x0.z * a0.z + x0.w * a0.w
                    + x1.x * a1.x + x1.y * a1.y + x1.z * a1.z + x1.w * a1.w + sp;
            #pragma unroll
            for (int o = 16; o; o >>= 1) s += __shfl_xor_sync(0xffffffffu, s, o);
            if (lane == 0) sh[row] = s + __ldg(&r1b2[row]) + __ldg(&r1bp[row]);
        }
    }
    __syncthreads();
    bcast32(sh, rank);
    CLUSTER_SYNC();

    // rb2
    ln256(sh, r2lg, r2lb, sa, red);
    gemv_slice(r2w1, r2b1, sa, st, rank, 1);
    bcast32(st, rank);
    CLUSTER_SYNC();
    gemv_slice(r2w2, r2b2, st, sh, rank, 2);
    bcast32(sh, rank);
    CLUSTER_SYNC();

    // attention (tokens identical -> o == v)
    ln256(sh, alg, alb, sa, red);
    gemv_slice(awin + 2 * HH * HH, abin + 2 * HH, sa, st, rank, 0);
    bcast32(st, rank);
    CLUSTER_SYNC();
    gemv_slice(awout, about_, st, sb, rank, 0);
    bcast32(sb, rank);
    CLUSTER_SYNC();
    gemv_slice(ow, ob, sb, st, rank, 0);
    bcast32(st, rank);
    CLUSTER_SYNC();

    // final logits on rank 0 (st fully assembled)
    if (rank == 0) {
        const float hv = st[tid];
        const float f0 = __ldg(&fw[tid]) + __ldg(&fw[HH + tid]);
        const float f1 = __ldg(&fw[2 * HH + tid]) + __ldg(&fw[3 * HH + tid]);
        const float l0 = bred8(f0 * hv, red) + fb[0];
        const float l1 = bred8(f1 * hv, red) + fb[1];
        if (tid == 0) g_c[b] = expf(l1 - l0);
    }
}

// ---------- fill (R16 structure; forced 8 blocks/SM) ----------
__device__ __forceinline__ float edge_val(float ux, float uy, float cb) {
    const float w0 = 1e-10f - __logf(ux + 1e-10f);
    const float w1 = 1e-10f - __logf(uy + 1e-10f);
    const float cw0 = cb * w0;
    const float d = w1 - cw0;
    const float margin = 3e-6f * (fabsf(w1) + fabsf(cw0)) + 2e-7f;
    if (fabsf(d) > margin) return d >= 0.f ? 1.0f : 0.0f;
    const float e0 = 1e-10f - logf(ux + 1e-10f);
    const float e1 = 1e-10f - logf(uy + 1e-10f);
    return (e1 >= cb * e0) ? 1.0f : 0.0f;
}

__global__ void __launch_bounds__(256, 8) fill_adj_kernel(const float2* __restrict__ u2,
                                                          float* __restrict__ out) {
    const int b = blockIdx.y;
    const int tl = blockIdx.x;
    int r = (int)((33.0f - sqrtf(1089.0f - 8.0f * (float)tl)) * 0.5f);
    while (r > 0 && r * (33 - r) / 2 > tl) r--;
    while ((r + 1) * (33 - (r + 1)) / 2 <= tl) r++;
    const int c = r + (tl - r * (33 - r) / 2);
    const int i0 = r << 6, j0 = c << 6;

    const float cb = g_c[b];
    const float2* __restrict__ ub = u2 + (size_t)b * PP;
    float* __restrict__ obp = out + (size_t)b * NN * NN;
    __shared__ float tile[64][65];   // stored TRANSPOSED: tile[jloc][iloc]

    const int tx = threadIdx.x;      // 0..15
    const int ty = threadIdx.y;      // 0..15

    if (i0 != j0) {
        #pragma unroll
        for (int rr = 0; rr < 4; rr++) {
            const int ti = ty + (rr << 4);
            const int i = i0 + ti;
            const int rowbase = (i * (2047 - i)) / 2 - i - 1 + j0;
            const int p0 = rowbase + 4 * tx;
            float4 ev;
            if (!(rowbase & 1)) {
                const float4* u4 = (const float4*)ub;
                const float4 A = __ldg(&u4[p0 >> 1]);
                const float4 Bq = __ldg(&u4[(p0 >> 1) + 1]);
                ev.x = edge_val(A.x,  A.y,  cb);
                ev.y = edge_val(A.z,  A.w,  cb);
                ev.z = edge_val(Bq.x, Bq.y, cb);
                ev.w = edge_val(Bq.z, Bq.w, cb);
            } else {
                const float2 a = __ldg(&ub[p0]);
                const float2 bq = __ldg(&ub[p0 + 1]);
                const float2 cq = __ldg(&ub[p0 + 2]);
                const float2 dq = __ldg(&ub[p0 + 3]);
                ev.x = edge_val(a.x,  a.y,  cb);
                ev.y = edge_val(bq.x, bq.y, cb);
                ev.z = edge_val(cq.x, cq.y, cb);
                ev.w = edge_val(dq.x, dq.y, cb);
            }
            __stcs((float4*)&obp[(size_t)i * NN + j0 + 4 * tx], ev);  // streaming store
            tile[4 * tx + 0][ti] = ev.x;
            tile[4 * tx + 1][ti] = ev.y;
            tile[4 * tx + 2][ti] = ev.z;
            tile[4 * tx + 3][ti] = ev.w;
        }
        __syncthreads();
        #pragma unroll
        for (int rr = 0; rr < 4; rr++) {
            const int tj = ty + (rr << 4);
            float4 f;
            f.x = tile[tj][4 * tx + 0];
            f.y = tile[tj][4 * tx + 1];
            f.z = tile[tj][4 * tx + 2];
            f.w = tile[tj][4 * tx + 3];
            __stcs((float4*)&obp[(size_t)(j0 + tj) * NN + i0 + 4 * tx], f);
        }
    } else {
        #pragma unroll
        for (int rr = 0; rr < 4; rr++) {
            const int ti = ty + (rr << 4);
            const int i = i0 + ti;
            const int rowbase = (i * (2047 - i)) / 2 - i - 1 + j0;
            #pragma unroll
            for (int k = 0; k < 4; k++) {
                const int col = 4 * tx + k;
                float e = 0.f;
                if (col > ti) {
                    const float2 uu = __ldg(&ub[rowbase + col]);
                    e = edge_val(uu.x, uu.y, cb);
                }
                tile[col][ti] = e;
                if (col >= ti) __stcs(&obp[(size_t)i * NN + j0 + col], e);
            }
        }
        __syncthreads();
        #pragma unroll
        for (int rr = 0; rr < 4; rr++) {
            const int tj = ty + (rr << 4);
            #pragma unroll
            for (int k = 0; k < 4; k++) {
                const int col = 4 * tx + k;
                if (col < tj) __stcs(&obp[(size_t)(j0 + tj) * NN + i0 + col], tile[tj][col]);
            }
        }
    }
}

extern "C" void kernel_launch(void* const* d_in, const int* in_sizes, int n_in,
                              void* d_out, int out_size) {
    Ptrs P;
    for (int i = 0; i < 30; i++) P.p[i] = (const float*)d_in[i];

    logits_cluster<<<BB * CSZ, 256>>>(P);

    dim3 grid(NTILE, BB), blk(16, 16);
    fill_adj_kernel<<<grid, blk>>>((const float2*)d_in[2], (float*)d_out);
}